// round 4
// baseline (speedup 1.0000x reference)
#include <cuda_runtime.h>
#include <math.h>

#define NROWS 65536
#define K1 512
#define A3C 64
#define CW 16
#define DT 8
#define PPC 96

typedef unsigned long long ull;

// ---- packed f32x2 helpers (FFMA2: 2 fp32 FMAs per issue slot) ---------------
__device__ __forceinline__ ull ffma2(ull a, ull b, ull c) {
    ull d;
    asm("fma.rn.f32x2 %0, %1, %2, %3;" : "=l"(d) : "l"(a), "l"(b), "l"(c));
    return d;
}
__device__ __forceinline__ ull bcast2(float x) {
    ull d;
    asm("mov.b64 %0, {%1, %1};" : "=l"(d) : "f"(x));
    return d;
}
__device__ __forceinline__ float2 unpack2(ull v) {
    float2 r;
    asm("mov.b64 {%0, %1}, %2;" : "=f"(r.x), "=f"(r.y) : "l"(v));
    return r;
}

// ---------------- scratch (device globals; no runtime allocation) -------------
__device__ float g_t[(size_t)NROWS * A3C];            // normalized t        16 MB
__device__ float g_h[(size_t)DT * NROWS * A3C];       // tower pre-BN h     134 MB
__device__ float g_ps[(size_t)DT * A3C * 512];        // partial sums
__device__ float g_pq[(size_t)DT * A3C * 512];        // partial sumsq
__device__ float g_scale[DT * A3C];                   // rsig*gamma
__device__ float g_shift[DT * A3C];                   // beta - mu*scale

// ---------------- kernel 1: t = normalize(x @ B) ------------------------------
// block: 256 thr, tile 128 rows x 64 cols, K-tiles of 32. reg tile 4x8 (FFMA2).
__global__ __launch_bounds__(256) void k1_gemm_norm(const float* __restrict__ x,
                                                    const float* __restrict__ B) {
    __shared__ __align__(16) float Xs[32 * 129];   // k-major, padded (conflict-free stores)
    __shared__ __align__(16) float Bs[32 * 64];
    __shared__ float invs[128];
    int tid = threadIdx.x;
    int tx = tid & 7, ty = tid >> 3;          // tx: 8 col-groups of 8, ty: 32 row-groups of 4
    int n0 = blockIdx.x * 128;

    ull acc2[4][4];                            // 4 rows x 4 col-pairs
#pragma unroll
    for (int j = 0; j < 4; j++)
#pragma unroll
        for (int c = 0; c < 4; c++) acc2[j][c] = 0ull;

    for (int kt = 0; kt < 16; kt++) {
        int k0 = kt * 32;
#pragma unroll
        for (int i = 0; i < 4; i++) {
            int l = tid + i * 256;            // 0..1023
            int r = l >> 3, kk4 = l & 7;
            float4 v = *(const float4*)(x + (size_t)(n0 + r) * K1 + k0 + kk4 * 4);
            Xs[(kk4 * 4 + 0) * 129 + r] = v.x;
            Xs[(kk4 * 4 + 1) * 129 + r] = v.y;
            Xs[(kk4 * 4 + 2) * 129 + r] = v.z;
            Xs[(kk4 * 4 + 3) * 129 + r] = v.w;
        }
#pragma unroll
        for (int i = 0; i < 2; i++) {
            int l = tid + i * 256;            // 0..511
            int kk = l >> 4, c4 = l & 15;
            *(float4*)(Bs + kk * 64 + c4 * 4) =
                *(const float4*)(B + (size_t)(k0 + kk) * 64 + c4 * 4);
        }
        __syncthreads();
#pragma unroll
        for (int kk = 0; kk < 32; kk++) {
            ull A[4];
#pragma unroll
            for (int j = 0; j < 4; j++) A[j] = bcast2(Xs[kk * 129 + ty * 4 + j]);
            const ulonglong2* wp = (const ulonglong2*)(Bs + kk * 64 + tx * 8);
            ulonglong2 w01 = wp[0];
            ulonglong2 w23 = wp[1];
            ull wv0 = w01.x, wv1 = w01.y, wv2 = w23.x, wv3 = w23.y;
#pragma unroll
            for (int j = 0; j < 4; j++) {
                acc2[j][0] = ffma2(A[j], wv0, acc2[j][0]);
                acc2[j][1] = ffma2(A[j], wv1, acc2[j][1]);
                acc2[j][2] = ffma2(A[j], wv2, acc2[j][2]);
                acc2[j][3] = ffma2(A[j], wv3, acc2[j][3]);
            }
        }
        __syncthreads();
    }
    // unpack
    float accs[4][8];
#pragma unroll
    for (int j = 0; j < 4; j++)
#pragma unroll
        for (int c = 0; c < 4; c++) {
            float2 u = unpack2(acc2[j][c]);
            accs[j][2 * c] = u.x; accs[j][2 * c + 1] = u.y;
        }
    // row L2-norm reduce across the 8 tx groups (reuse Bs)
    float* ps = Bs;
#pragma unroll
    for (int j = 0; j < 4; j++) {
        float s = 0.f;
#pragma unroll
        for (int c = 0; c < 8; c++) s += accs[j][c] * accs[j][c];
        ps[(ty * 4 + j) * 8 + tx] = s;
    }
    __syncthreads();
    if (tid < 128) {
        float s = 0.f;
#pragma unroll
        for (int q = 0; q < 8; q++) s += ps[tid * 8 + q];
        float nrm = sqrtf(s);
        invs[tid] = 1.f / fmaxf(nrm, 1e-12f);
    }
    __syncthreads();
#pragma unroll
    for (int j = 0; j < 4; j++) {
        int r = ty * 4 + j;
        float inv = invs[r];
        float4 o0, o1;
        o0.x = accs[j][0] * inv; o0.y = accs[j][1] * inv; o0.z = accs[j][2] * inv; o0.w = accs[j][3] * inv;
        o1.x = accs[j][4] * inv; o1.y = accs[j][5] * inv; o1.z = accs[j][6] * inv; o1.w = accs[j][7] * inv;
        *(float4*)(g_t + (size_t)(n0 + r) * 64 + tx * 8)     = o0;
        *(float4*)(g_t + (size_t)(n0 + r) * 64 + tx * 8 + 4) = o1;
    }
}

// ---------------- kernel 2: windowed affine sum -> rep -----------------------
__global__ __launch_bounds__(256) void k2_window(const float* __restrict__ lw,
                                                 const float* __restrict__ lb,
                                                 float* __restrict__ rep) {
    __shared__ float ts[143 * 64];
    int tid = threadIdx.x;
    int a = tid & 63, rg = tid >> 6;          // a: feature, rg: 0..3
    int R0 = blockIdx.x * 128;

    for (int l = tid; l < 143 * 64; l += 256) {
        int s = l >> 6, aa = l & 63;
        int g = R0 - 15 + s;
        ts[l] = (g >= 0) ? g_t[(size_t)g * 64 + aa] : 0.f;
    }
    float w[CW];
    float bs = 0.f;
#pragma unroll
    for (int j = 0; j < CW; j++) { w[j] = lw[j * 64 + a]; bs += lb[j * 64 + a]; }
    __syncthreads();

    for (int m = 0; m < 32; m++) {
        int r = m * 4 + rg;
        int i = R0 + r;
        float acc = bs;
        if (i >= CW - 1) {
#pragma unroll
            for (int j = 0; j < CW; j++) acc += w[j] * ts[(r + j) * 64 + a];
        } else {
#pragma unroll
            for (int j = 0; j < CW; j++) {
                int g = min(j, i);
                acc += w[j] * ts[(g + 15) * 64 + a];
            }
        }
        rep[(size_t)i * 64 + a] = acc;
    }
}

// ---------------- kernel 3: h[d] = rep @ W1[d] + b1[d], + BN partials --------
__global__ __launch_bounds__(256) void k3_gemm_h(const float* __restrict__ rep,
                                                 const float* __restrict__ W1,
                                                 const float* __restrict__ b1) {
    __shared__ __align__(16) float Rs[32 * 129];
    __shared__ __align__(16) float Ws[64 * 64];
    int tid = threadIdx.x;
    int tx = tid & 7, ty = tid >> 3;
    int d = blockIdx.y;
    int n0 = blockIdx.x * 128;

#pragma unroll
    for (int i = 0; i < 4; i++) {
        int l = tid + i * 256;
        *(float4*)(Ws + l * 4) = *(const float4*)(W1 + (size_t)d * 4096 + l * 4);
    }
    ull acc2[4][4];
#pragma unroll
    for (int j = 0; j < 4; j++)
#pragma unroll
        for (int c = 0; c < 4; c++) acc2[j][c] = 0ull;

    for (int kt = 0; kt < 2; kt++) {
        int k0 = kt * 32;
#pragma unroll
        for (int i = 0; i < 4; i++) {
            int l = tid + i * 256;
            int r = l >> 3, kk4 = l & 7;
            float4 v = *(const float4*)(rep + (size_t)(n0 + r) * 64 + k0 + kk4 * 4);
            Rs[(kk4 * 4 + 0) * 129 + r] = v.x;
            Rs[(kk4 * 4 + 1) * 129 + r] = v.y;
            Rs[(kk4 * 4 + 2) * 129 + r] = v.z;
            Rs[(kk4 * 4 + 3) * 129 + r] = v.w;
        }
        __syncthreads();
#pragma unroll
        for (int kk = 0; kk < 32; kk++) {
            ull A[4];
#pragma unroll
            for (int j = 0; j < 4; j++) A[j] = bcast2(Rs[kk * 129 + ty * 4 + j]);
            const ulonglong2* wp = (const ulonglong2*)(Ws + (k0 + kk) * 64 + tx * 8);
            ulonglong2 w01 = wp[0];
            ulonglong2 w23 = wp[1];
            ull wv0 = w01.x, wv1 = w01.y, wv2 = w23.x, wv3 = w23.y;
#pragma unroll
            for (int j = 0; j < 4; j++) {
                acc2[j][0] = ffma2(A[j], wv0, acc2[j][0]);
                acc2[j][1] = ffma2(A[j], wv1, acc2[j][1]);
                acc2[j][2] = ffma2(A[j], wv2, acc2[j][2]);
                acc2[j][3] = ffma2(A[j], wv3, acc2[j][3]);
            }
        }
        __syncthreads();
    }
    float accs[4][8];
#pragma unroll
    for (int j = 0; j < 4; j++)
#pragma unroll
        for (int c = 0; c < 4; c++) {
            float2 u = unpack2(acc2[j][c]);
            accs[j][2 * c] = u.x; accs[j][2 * c + 1] = u.y;
        }
    // epilogue: +b1, write h, BN partial sums
    float bb[8];
#pragma unroll
    for (int c = 0; c < 8; c++) bb[c] = b1[d * 64 + tx * 8 + c];
    float s[8], q[8];
#pragma unroll
    for (int c = 0; c < 8; c++) { s[c] = 0.f; q[c] = 0.f; }
#pragma unroll
    for (int j = 0; j < 4; j++) {
        int r = ty * 4 + j;
        float v0 = accs[j][0] + bb[0], v1 = accs[j][1] + bb[1], v2 = accs[j][2] + bb[2], v3 = accs[j][3] + bb[3];
        float v4 = accs[j][4] + bb[4], v5 = accs[j][5] + bb[5], v6 = accs[j][6] + bb[6], v7 = accs[j][7] + bb[7];
        s[0] += v0; s[1] += v1; s[2] += v2; s[3] += v3; s[4] += v4; s[5] += v5; s[6] += v6; s[7] += v7;
        q[0] += v0*v0; q[1] += v1*v1; q[2] += v2*v2; q[3] += v3*v3;
        q[4] += v4*v4; q[5] += v5*v5; q[6] += v6*v6; q[7] += v7*v7;
        float4 o0, o1;
        o0.x = v0; o0.y = v1; o0.z = v2; o0.w = v3;
        o1.x = v4; o1.y = v5; o1.z = v6; o1.w = v7;
        float* hp = g_h + (size_t)d * NROWS * 64 + (size_t)(n0 + r) * 64 + tx * 8;
        *(float4*)(hp) = o0;
        *(float4*)(hp + 4) = o1;
    }
    float* psum = Rs;            // 2048 floats
    float* psq  = Rs + 2048;     // 2048 floats (Rs has 4128)
#pragma unroll
    for (int c = 0; c < 8; c++) {
        psum[ty * 64 + tx * 8 + c] = s[c];
        psq [ty * 64 + tx * 8 + c] = q[c];
    }
    __syncthreads();
    if (tid < 64) {
        float S = 0.f, Q = 0.f;
#pragma unroll
        for (int t2 = 0; t2 < 32; t2++) { S += psum[t2 * 64 + tid]; Q += psq[t2 * 64 + tid]; }
        g_ps[((size_t)d * 64 + tid) * 512 + blockIdx.x] = S;
        g_pq[((size_t)d * 64 + tid) * 512 + blockIdx.x] = Q;
    }
}

// ---------------- kernel 4: deterministic BN stats reduce --------------------
__global__ __launch_bounds__(128) void k4_stats(const float* __restrict__ gamma,
                                                const float* __restrict__ beta) {
    int id = blockIdx.x;            // d*64 + c
    int tid = threadIdx.x;
    float S = 0.f, Q = 0.f;
    for (int i = tid; i < 512; i += 128) {
        S += g_ps[(size_t)id * 512 + i];
        Q += g_pq[(size_t)id * 512 + i];
    }
    __shared__ float ss[128], qq[128];
    ss[tid] = S; qq[tid] = Q;
    __syncthreads();
    for (int off = 64; off > 0; off >>= 1) {
        if (tid < off) { ss[tid] += ss[tid + off]; qq[tid] += qq[tid + off]; }
        __syncthreads();
    }
    if (tid == 0) {
        float mu  = ss[0] * (1.f / 65536.f);
        float var = qq[0] * (1.f / 65536.f) - mu * mu;
        float rs  = rsqrtf(fmaxf(var, 0.f) + 1e-5f);
        float sc  = rs * gamma[id];
        g_scale[id] = sc;
        g_shift[id] = beta[id] - mu * sc;
    }
}

// ---------------- kernel 5: BN+ELU, GEMM2, write interleaved out directly ----
// grid (8, 512): blockIdx.x = d (fast-varying so the 8 d-blocks of one row-tile
// are concurrent and their stride-8 stores combine in L2 lines of `out`).
__global__ __launch_bounds__(256) void k5_bn_gemm2(const float* __restrict__ W2,
                                                   const float* __restrict__ b2,
                                                   float* __restrict__ out) {
    __shared__ __align__(16) float Hs[32 * 129];
    __shared__ __align__(16) float Ws[64 * 96];
    __shared__ float sA[64], sB[64];
    int tid = threadIdx.x;
    int tx = tid & 15, ty = tid >> 4;   // tx: 16 col-groups of 6, ty: 16 row-groups of 8
    int d = blockIdx.x;
    int n0 = blockIdx.y * 128;

    if (tid < 64) { sA[tid] = g_scale[d * 64 + tid]; sB[tid] = g_shift[d * 64 + tid]; }
#pragma unroll
    for (int i = 0; i < 6; i++) {
        int l = tid + i * 256;
        *(float4*)(Ws + l * 4) = *(const float4*)(W2 + (size_t)d * 6144 + l * 4);
    }
    ull acc2[8][3];                      // 8 rows x 3 col-pairs (6 cols)
#pragma unroll
    for (int j = 0; j < 8; j++)
#pragma unroll
        for (int c = 0; c < 3; c++) acc2[j][c] = 0ull;
    __syncthreads();

    for (int kt = 0; kt < 2; kt++) {
        int k0 = kt * 32;
#pragma unroll
        for (int i = 0; i < 4; i++) {
            int l = tid + i * 256;
            int r = l >> 3, kk4 = l & 7;
            float4 v = *(const float4*)(g_h + (size_t)d * NROWS * 64 +
                                        (size_t)(n0 + r) * 64 + k0 + kk4 * 4);
            int b0 = k0 + kk4 * 4;
            float e;
            e = v.x * sA[b0 + 0] + sB[b0 + 0]; e = e > 0.f ? e : expm1f(e); Hs[(kk4*4+0)*129 + r] = e;
            e = v.y * sA[b0 + 1] + sB[b0 + 1]; e = e > 0.f ? e : expm1f(e); Hs[(kk4*4+1)*129 + r] = e;
            e = v.z * sA[b0 + 2] + sB[b0 + 2]; e = e > 0.f ? e : expm1f(e); Hs[(kk4*4+2)*129 + r] = e;
            e = v.w * sA[b0 + 3] + sB[b0 + 3]; e = e > 0.f ? e : expm1f(e); Hs[(kk4*4+3)*129 + r] = e;
        }
        __syncthreads();
#pragma unroll
        for (int kk = 0; kk < 32; kk++) {
            const ull* wp = (const ull*)(Ws + (k0 + kk) * 96 + tx * 6);   // 8B-aligned (24B steps)
            ull w0 = wp[0], w1 = wp[1], w2 = wp[2];
#pragma unroll
            for (int j = 0; j < 8; j++) {
                ull A = bcast2(Hs[kk * 129 + ty * 8 + j]);
                acc2[j][0] = ffma2(A, w0, acc2[j][0]);
                acc2[j][1] = ffma2(A, w1, acc2[j][1]);
                acc2[j][2] = ffma2(A, w2, acc2[j][2]);
            }
        }
        __syncthreads();
    }
    float bb[6];
#pragma unroll
    for (int c = 0; c < 6; c++) bb[c] = b2[d * 96 + tx * 6 + c];
#pragma unroll
    for (int j = 0; j < 8; j++) {
        int n = n0 + ty * 8 + j;
        float* op = out + (size_t)n * 768 + (tx * 6) * 8 + d;   // y_1[n, p*8 + d]
        float2 u0 = unpack2(acc2[j][0]);
        float2 u1 = unpack2(acc2[j][1]);
        float2 u2 = unpack2(acc2[j][2]);
        op[0 * 8] = u0.x + bb[0];
        op[1 * 8] = u0.y + bb[1];
        op[2 * 8] = u1.x + bb[2];
        op[3 * 8] = u1.y + bb[3];
        op[4 * 8] = u2.x + bb[4];
        op[5 * 8] = u2.y + bb[5];
    }
}

// ---------------- launcher ----------------------------------------------------
extern "C" void kernel_launch(void* const* d_in, const int* in_sizes, int n_in,
                              void* d_out, int out_size) {
    const float* x     = (const float*)d_in[0];
    const float* B     = (const float*)d_in[1];
    const float* lw    = (const float*)d_in[2];
    const float* lb    = (const float*)d_in[3];
    const float* W1    = (const float*)d_in[4];
    const float* b1    = (const float*)d_in[5];
    const float* gamma = (const float*)d_in[6];
    const float* beta  = (const float*)d_in[7];
    const float* W2    = (const float*)d_in[8];
    const float* b2    = (const float*)d_in[9];
    // flag (d_in[10]) == 1 and label unused in forward; shapes fix the flag=1 path.

    float* out = (float*)d_out;
    float* rep = out + (size_t)NROWS * (PPC * DT);   // rep section after y_1

    k1_gemm_norm<<<512, 256>>>(x, B);
    k2_window<<<512, 256>>>(lw, lb, rep);
    k3_gemm_h<<<dim3(512, 8), 256>>>(rep, W1, b1);
    k4_stats<<<512, 128>>>(gamma, beta);
    k5_bn_gemm2<<<dim3(8, 512), 256>>>(W2, b2, out);
}